// round 15
// baseline (speedup 1.0000x reference)
#include <cuda_runtime.h>
#include <cuda_bf16.h>
#include <math.h>

// Problem dims (fixed by the reference)
#define E     1024
#define H     2048
#define G     8192     // 4*H gate rows
#define TT    128      // title timesteps
#define TA    16       // author timesteps
#define NB    148      // persistent grid: one block per SM
#define NT    512      // threads per block (16 warps)
#define UPB   14       // hidden units per block (148*14 = 2072 >= 2048)
#define SMU   13       // units whose title weights live in smem (52 rows = 208 KB bf16)
#define WELEM ((size_t)G * H)
#define XS_STRIDE 1028                    // floats per staged X row (conflict-free, 16B-aligned)
#define WS_BYTES (SMU * 4 * H * 2)        // 212992 B smem weights
#define DYN_SMEM 213504                   // covers weights phase AND gemm stage (147968)

// ---------------- device scratch (no allocation allowed) ----------------
__device__ __align__(16) float g_gx_t[TT * G];
__device__ __align__(16) float g_gx_a[TA * G];
__device__ __align__(16) __nv_bfloat16 g_Wa_bf[WELEM];        // authors bf16 (32 MB)
__device__ __align__(16) __nv_bfloat16 g_Wt13_bf[NB * 4 * H]; // per-block title unit-13 rows
__device__ __align__(16) float g_h_t[2 * H];
__device__ __align__(16) float g_h_a[2 * H];
__device__ __align__(16) float g_h1[H];
__device__ __align__(16) float g_h2[H];
__device__ unsigned g_arrive;
__device__ unsigned g_gen;

// ---------------- packed f32x2 + bf16 helpers ----------------
typedef unsigned long long ull;
__device__ __forceinline__ ull packf2(float x, float y) {
    ull d; asm("mov.b64 %0, {%1, %2};" : "=l"(d) : "f"(x), "f"(y)); return d;
}
__device__ __forceinline__ void unpackf2(ull d, float& x, float& y) {
    asm("mov.b64 {%0, %1}, %2;" : "=f"(x), "=f"(y) : "l"(d));
}
__device__ __forceinline__ void ffma2(ull& d, ull a, ull b) {
    asm("fma.rn.f32x2 %0, %1, %2, %0;" : "+l"(d) : "l"(a), "l"(b));
}
__device__ __forceinline__ ull addf2(ull a, ull b) {
    ull d; asm("add.rn.f32x2 %0, %1, %2;" : "=l"(d) : "l"(a), "l"(b)); return d;
}
__device__ __forceinline__ ull b2f2(unsigned w) {     // bf16x2 -> f32x2 via 2 PRMT
    unsigned lo, hi, z = 0u;
    asm("prmt.b32 %0, %1, %2, 0x1044;" : "=r"(lo) : "r"(w), "r"(z));
    asm("prmt.b32 %0, %1, %2, 0x3244;" : "=r"(hi) : "r"(w), "r"(z));
    ull d; asm("mov.b64 %0, {%1, %2};" : "=l"(d) : "r"(lo), "r"(hi));
    return d;
}

// fast activations (err ~2^-21, negligible vs bf16 weight noise)
__device__ __forceinline__ float sigf(float x)      { return __fdividef(1.f, 1.f + __expf(-x)); }
__device__ __forceinline__ float tanhfast(float x)  { return __fdividef(2.f, 1.f + __expf(-2.f * x)) - 1.f; }

// ---------------- fence-free release/acquire grid barrier ----------------
__device__ __forceinline__ void bar_arrive(unsigned target) {
    unsigned old;
    asm volatile("atom.acq_rel.gpu.add.u32 %0, [%1], %2;"
                 : "=r"(old) : "l"(&g_arrive), "r"(1u) : "memory");
    if (old == NB - 1) {
        asm volatile("st.relaxed.gpu.u32 [%0], %1;" :: "l"(&g_arrive), "r"(0u) : "memory");
        asm volatile("st.release.gpu.u32 [%0], %1;" :: "l"(&g_gen), "r"(target) : "memory");
    }
}
__device__ __forceinline__ void bar_wait(unsigned target) {
    unsigned g;
    do {
        asm volatile("ld.acquire.gpu.u32 %0, [%1];" : "=r"(g) : "l"(&g_gen) : "memory");
    } while (g < target);
}
__device__ __forceinline__ void grid_sync_all(unsigned target) {
    __syncthreads();
    if (threadIdx.x == 0) { bar_arrive(target); bar_wait(target); }
    __syncthreads();
}

// ---------------- init: zero h buffers + barrier counters ----------------
__global__ void init_kernel() {
    int i = blockIdx.x * blockDim.x + threadIdx.x;
    if (i < 2 * H)          g_h_t[i] = 0.f;
    else if (i < 4 * H)     g_h_a[i - 2 * H] = 0.f;
    if (i == 0) { g_arrive = 0u; g_gen = 0u; }
}

// ---------------- in-block x-side GEMM: gx[t][row] for OWN rows ----------------
// X tile (<=32 t) staged in smem; warp stages its W_ih row to wbuf then lane=t dots.
__device__ __forceinline__ void xgemm_block(const int* __restrict__ idx,
                                            const float* __restrict__ emb,
                                            const float* __restrict__ Wih,
                                            const float* __restrict__ bih,
                                            const float* __restrict__ bhh,
                                            float* __restrict__ gxout, int Ttot,
                                            float* __restrict__ Xs, float* __restrict__ wbuf,
                                            int u0, int nu, int tid, int warp, int lane) {
    const int nrows = 4 * nu;
    for (int t0 = 0; t0 < Ttot; t0 += 32) {
        int tn = Ttot - t0; if (tn > 32) tn = 32;
        for (int e = tid; e < tn * E; e += NT) {
            int t = e >> 10, k = e & 1023;
            Xs[t * XS_STRIDE + k] = __ldg(emb + (size_t)__ldg(idx + t0 + t) * E + k);
        }
        __syncthreads();
        for (int r = warp; r < nrows; r += 16) {
            int ul = r >> 2, g = r & 3;
            int grow = g * H + u0 + ul;
            const float4* w4 = (const float4*)(Wih + (size_t)grow * E);
            float4* wb = (float4*)(wbuf + warp * E);
#pragma unroll
            for (int j = 0; j < 8; j++) wb[(j << 5) + lane] = __ldg(w4 + ((j << 5) + lane));
            __syncwarp();
            if (lane < tn) {
                const float* xr = Xs + lane * XS_STRIDE;
                float acc = 0.f;
#pragma unroll 8
                for (int kc = 0; kc < 256; kc++) {
                    float4 w = wb[kc];                       // broadcast
                    float4 x = *(const float4*)(xr + 4 * kc);
                    acc = fmaf(w.x, x.x, fmaf(w.y, x.y, fmaf(w.z, x.z, fmaf(w.w, x.w, acc))));
                }
                gxout[(size_t)(t0 + lane) * G + grow] = acc + __ldg(bih + grow) + __ldg(bhh + grow);
            }
            __syncwarp();
        }
        __syncthreads();
    }
}

// ---------------- step helpers ----------------
// lane's 64-element h slice (matches weight uint4 layout), packed into 32 f32x2
__device__ __forceinline__ void load_hslice(ull hp[32], const float* __restrict__ hsrc, int lane) {
    const float4* h4 = (const float4*)hsrc;
#pragma unroll
    for (int k = 0; k < 8; k++) {
        float4 f0 = __ldcg(h4 + ((k << 6) + (lane << 1)));
        float4 f1 = __ldcg(h4 + ((k << 6) + (lane << 1) + 1));
        hp[4 * k + 0] = packf2(f0.x, f0.y);
        hp[4 * k + 1] = packf2(f0.z, f0.w);
        hp[4 * k + 2] = packf2(f1.x, f1.y);
        hp[4 * k + 3] = packf2(f1.z, f1.w);
    }
}

template<bool SMEM>
__device__ __forceinline__ uint4 wload(const uint4* p, int c4) {
    if (SMEM) return p[c4];
    return __ldcg(p + c4);   // in-kernel-written global: bypass (stale) L1
}

// full unit update: 4 gate rows + reduce + pointwise + h store. c lives in lane0 reg.
template<bool SMEM>
__device__ __forceinline__ void unit_step(const __nv_bfloat16* __restrict__ wbase, size_t gstride,
                                          const ull hp[32], const float* __restrict__ gx,
                                          int u, float& c, float* __restrict__ hout, int lane) {
    float s[4];
#pragma unroll
    for (int g = 0; g < 4; g++) {
        const uint4* w = (const uint4*)(wbase + gstride * g);
        ull a0 = 0, a1 = 0, a2 = 0, a3 = 0;
#pragma unroll
        for (int half = 0; half < 2; half++) {
            uint4 v[4];
#pragma unroll
            for (int j = 0; j < 4; j++) v[j] = wload<SMEM>(w, ((((half << 2) + j) << 5) + lane));
#pragma unroll
            for (int j = 0; j < 4; j++) {
                int kk = (half << 2) + j;
                ffma2(a0, b2f2(v[j].x), hp[4 * kk + 0]);
                ffma2(a1, b2f2(v[j].y), hp[4 * kk + 1]);
                ffma2(a2, b2f2(v[j].z), hp[4 * kk + 2]);
                ffma2(a3, b2f2(v[j].w), hp[4 * kk + 3]);
            }
        }
        float x, y;
        unpackf2(addf2(addf2(a0, a1), addf2(a2, a3)), x, y);
        s[g] = x + y;
    }
#pragma unroll
    for (int g = 0; g < 4; g++)
#pragma unroll
        for (int off = 16; off; off >>= 1) s[g] += __shfl_xor_sync(0xFFFFFFFFu, s[g], off);
    if (lane == 0) {
        float gi = s[0] + gx[0 * H + u];
        float gf = s[1] + gx[1 * H + u];
        float gg = s[2] + gx[2 * H + u];
        float go = s[3] + gx[3 * H + u];
        float iv = sigf(gi), fv = sigf(gf), gv = tanhfast(gg), ov = sigf(go);
        float cn = fv * c + iv * gv;
        c = cn;
        __stcg(hout + u, ov * tanhfast(cn));
    }
}

__device__ __forceinline__ float warp_dot(const float* __restrict__ Wrow,
                                          const float* __restrict__ shv, int K, int lane) {
    const float4* w4 = (const float4*)Wrow;
    const float4* s4 = (const float4*)shv;
    float acc = 0.f;
    for (int i = lane; i < K / 4; i += 32) {
        float4 w = __ldg(w4 + i), x = s4[i];
        acc = fmaf(w.x, x.x, fmaf(w.y, x.y, fmaf(w.z, x.z, fmaf(w.w, x.w, acc))));
    }
#pragma unroll
    for (int off = 16; off; off >>= 1) acc += __shfl_xor_sync(0xFFFFFFFFu, acc, off);
    return acc;
}

// ---------------- the single persistent kernel ----------------
__global__ __launch_bounds__(NT, 1) void mono_kernel(
        const int* __restrict__ xt, const int* __restrict__ xa,
        const float* __restrict__ emb_t, const float* __restrict__ emb_a,
        const float* __restrict__ Wih_t, const float* __restrict__ Whh_t,
        const float* __restrict__ bih_t, const float* __restrict__ bhh_t,
        const float* __restrict__ Wih_a, const float* __restrict__ Whh_a,
        const float* __restrict__ bih_a, const float* __restrict__ bhh_a,
        const float* __restrict__ W1, const float* __restrict__ b1,
        const float* __restrict__ W2, const float* __restrict__ b2,
        const float* __restrict__ W3, const float* __restrict__ b3,
        float* __restrict__ out) {
    extern __shared__ __align__(16) unsigned char dynsm[];
    __nv_bfloat16* ws = (__nv_bfloat16*)dynsm;            // weights after prologue
    float* Xs   = (float*)dynsm;                           // gemm X stage (131584 B)
    float* wbuf = (float*)(dynsm + 131584);                // gemm W stage (16 KB)
    float* mstage = (float*)dynsm;                         // MLP stage

    const int tid = threadIdx.x, warp = tid >> 5, lane = tid & 31;
    const int b = blockIdx.x;
    const int u0 = b * UPB;
    int nu = 2048 - u0;
    if (nu < 0) nu = 0;
    if (nu > UPB) nu = UPB;
    const int n_sm = (nu < SMU) ? nu : SMU;

    // ---- Phase 0: x-side GEMMs (own rows only -> no cross-block sync needed) ----
    xgemm_block(xt, emb_t, Wih_t, bih_t, bhh_t, g_gx_t, TT, Xs, wbuf, u0, nu, tid, warp, lane);
    xgemm_block(xa, emb_a, Wih_a, bih_a, bhh_a, g_gx_a, TA, Xs, wbuf, u0, nu, tid, warp, lane);

    // ---- Phase 1: weight conversions ----
    {   // title units 0..n_sm-1 -> smem bf16 (unit-major, rows contiguous)
        unsigned* wsu = (unsigned*)ws;
        const int total = n_sm * 4 * (H / 2);
        for (int e = tid; e < total; e += NT) {
            int sr = e >> 10, wd = e & 1023;
            int ul = sr >> 2, g = sr & 3;
            float2 v = *(const float2*)(Whh_t + ((size_t)g * H + u0 + ul) * H + 2 * wd);
            __nv_bfloat162 p = __float22bfloat162_rn(v);
            wsu[(sr << 10) + wd] = *(unsigned*)&p;
        }
    }
    if (nu == UPB) {  // title unit 13 -> per-block global bf16
        unsigned* dst = (unsigned*)g_Wt13_bf + (size_t)b * 4 * (H / 2);
        for (int e = tid; e < 4 * (H / 2); e += NT) {
            int g = e >> 10, wd = e & 1023;
            float2 v = *(const float2*)(Whh_t + ((size_t)g * H + u0 + SMU) * H + 2 * wd);
            __nv_bfloat162 p = __float22bfloat162_rn(v);
            dst[(g << 10) + wd] = *(unsigned*)&p;
        }
    }
    {   // authors: cooperative full-matrix fp32 -> bf16
        const float2* src = (const float2*)Whh_a;
        unsigned* dst = (unsigned*)g_Wa_bf;
        for (size_t i = (size_t)b * NT + tid; i < WELEM / 2; i += (size_t)NB * NT) {
            float2 v = src[i];
            __nv_bfloat162 p = __float22bfloat162_rn(v);
            dst[i] = *(unsigned*)&p;
        }
    }
    float cT = 0.f, cA = 0.f;   // per-warp cell state (lane 0 authoritative)
    unsigned bar = 0;
    grid_sync_all(++bar);       // author weights ready chip-wide

    // ---- Phase 2: recurrence ----
    for (int t = 0; t < TT; t++) {
        const float* hsT = g_h_t + (size_t)(t & 1) * H;
        float*       hdT = g_h_t + (size_t)((t + 1) & 1) * H;
        const float* gxT = g_gx_t + (size_t)t * G;
        ull hp[32];
        if (warp < n_sm) {
            load_hslice(hp, hsT, lane);
            unit_step<true>(ws + ((size_t)(warp * 4) << 11), (size_t)H,
                            hp, gxT, u0 + warp, cT, hdT, lane);
        } else if (warp == SMU && nu == UPB) {
            load_hslice(hp, hsT, lane);
            unit_step<false>(g_Wt13_bf + (size_t)b * 4 * H, (size_t)H,
                             hp, gxT, u0 + SMU, cT, hdT, lane);
        }
        if (t < TA) {
            int au = 15 - warp;             // warps 15..2 own author units 0..13
            if (au >= 0 && au < nu) {
                const float* hsA = g_h_a + (size_t)(t & 1) * H;
                float*       hdA = g_h_a + (size_t)((t + 1) & 1) * H;
                load_hslice(hp, hsA, lane);
                unit_step<false>(g_Wa_bf + (size_t)(u0 + au) * H, (size_t)H * H,
                                 hp, g_gx_a + (size_t)t * G, u0 + au, cA, hdA, lane);
            }
        }
        __syncthreads();
        ++bar;
        if (tid == 0) { bar_arrive(bar); bar_wait(bar); }
        __syncthreads();
    }
    // final hT in g_h_t[0..H), final hA in g_h_a[0..H)  (TT, TA even)

    // ---- Phase 3: MLP head ----
    {
        const float4* t4 = (const float4*)g_h_t;
        const float4* a4 = (const float4*)g_h_a;
        float4* d4 = (float4*)mstage;
        for (int i = tid; i < H / 4; i += NT) {
            d4[i]         = __ldcg(t4 + i);
            d4[H / 4 + i] = __ldcg(a4 + i);
        }
        __syncthreads();
        if (warp < nu) {
            int row = u0 + warp;
            float s = warp_dot(W1 + (size_t)row * 2 * H, mstage, 2 * H, lane);
            if (lane == 0) __stcg(&g_h1[row], fmaxf(s + __ldg(b1 + row), 0.f));
        }
        grid_sync_all(++bar);
    }
    {
        const float4* s4 = (const float4*)g_h1;
        float4* d4 = (float4*)mstage;
        for (int i = tid; i < H / 4; i += NT) d4[i] = __ldcg(s4 + i);
        __syncthreads();
        if (warp < nu) {
            int row = u0 + warp;
            float s = warp_dot(W2 + (size_t)row * H, mstage, H, lane);
            if (lane == 0) __stcg(&g_h2[row], fmaxf(s + __ldg(b2 + row), 0.f));
        }
        grid_sync_all(++bar);
    }
    if (b == 0) {
        const float4* s4 = (const float4*)g_h2;
        float4* d4 = (float4*)mstage;
        for (int i = tid; i < H / 4; i += NT) d4[i] = __ldcg(s4 + i);
        __syncthreads();
        if (warp < 2) {
            float s = warp_dot(W3 + (size_t)warp * H, mstage, H, lane);
            if (lane == 0) out[warp] = s + __ldg(b3 + warp);
        }
    }
}

// ---------------- launcher ----------------
extern "C" void kernel_launch(void* const* d_in, const int* in_sizes, int n_in,
                              void* d_out, int out_size) {
    const int*   x_title   = (const int*)  d_in[0];
    const int*   x_authors = (const int*)  d_in[1];
    const float* emb_t     = (const float*)d_in[2];
    const float* emb_a     = (const float*)d_in[3];
    const float* W_ih_t    = (const float*)d_in[4];
    const float* W_hh_t    = (const float*)d_in[5];
    const float* b_ih_t    = (const float*)d_in[6];
    const float* b_hh_t    = (const float*)d_in[7];
    const float* W_ih_a    = (const float*)d_in[8];
    const float* W_hh_a    = (const float*)d_in[9];
    const float* b_ih_a    = (const float*)d_in[10];
    const float* b_hh_a    = (const float*)d_in[11];
    const float* W1        = (const float*)d_in[12];
    const float* b1        = (const float*)d_in[13];
    const float* W2        = (const float*)d_in[14];
    const float* b2        = (const float*)d_in[15];
    const float* W3        = (const float*)d_in[16];
    const float* b3        = (const float*)d_in[17];
    float* out = (float*)d_out;

    static int smem_set = 0;
    if (!smem_set) {
        cudaFuncSetAttribute(mono_kernel,
                             cudaFuncAttributeMaxDynamicSharedMemorySize, DYN_SMEM);
        smem_set = 1;
    }

    init_kernel<<<(4 * H + 255) / 256, 256>>>();
    mono_kernel<<<NB, NT, DYN_SMEM>>>(x_title, x_authors, emb_t, emb_a,
                                      W_ih_t, W_hh_t, b_ih_t, b_hh_t,
                                      W_ih_a, W_hh_a, b_ih_a, b_hh_a,
                                      W1, b1, W2, b2, W3, b3, out);
}

// round 16
// speedup vs baseline: 1.3551x; 1.3551x over previous
#include <cuda_runtime.h>
#include <cuda_bf16.h>
#include <math.h>

// Problem dims (fixed by the reference)
#define E     1024
#define H     2048
#define G     8192     // 4*H gate rows
#define TT    128      // title timesteps
#define TA    16       // author timesteps
#define NBLK  148      // persistent grid: one block per SM
#define NT    512      // threads per block (16 warps)
#define WELEM ((size_t)G * H)
#define WS_BYTES (13 * 4 * H * 2)           // 212992 B smem title weights (13 units)
#define HS_OFF   WS_BYTES                   // 8 KB split h staging
#define DYN_SMEM (WS_BYTES + 2 * H * 4)     // 221184 B

// ---------------- device scratch (no allocation allowed) ----------------
__device__ __align__(16) float g_gx_t[TT * G];
__device__ __align__(16) float g_gx_a[TA * G];
__device__ __align__(16) __nv_bfloat16 g_Wa_bf[WELEM];          // authors bf16 (32 MB)
__device__ __align__(16) __nv_bfloat16 g_Wt13_bf[NBLK * 4 * H]; // per-block 14th title unit
__device__ __align__(16) float g_h_t[2 * H];
__device__ __align__(16) float g_h_a[2 * H];
__device__ __align__(16) float g_h1[H];
__device__ __align__(16) float g_h2[H];
__device__ unsigned g_cnt[NBLK * 32];       // one padded line per block

// ---------------- packed f32x2 + bf16 helpers ----------------
typedef unsigned long long ull;
__device__ __forceinline__ ull packf2(float x, float y) {
    ull d; asm("mov.b64 %0, {%1, %2};" : "=l"(d) : "f"(x), "f"(y)); return d;
}
__device__ __forceinline__ void unpackf2(ull d, float& x, float& y) {
    asm("mov.b64 {%0, %1}, %2;" : "=f"(x), "=f"(y) : "l"(d));
}
__device__ __forceinline__ void ffma2(ull& d, ull a, ull b) {
    asm("fma.rn.f32x2 %0, %1, %2, %0;" : "+l"(d) : "l"(a), "l"(b));
}
__device__ __forceinline__ ull addf2(ull a, ull b) {
    ull d; asm("add.rn.f32x2 %0, %1, %2;" : "=l"(d) : "l"(a), "l"(b)); return d;
}
__device__ __forceinline__ ull b2f2(unsigned w) {     // bf16x2 -> f32x2 via 2 PRMT
    unsigned lo, hi, z = 0u;
    asm("prmt.b32 %0, %1, %2, 0x1044;" : "=r"(lo) : "r"(w), "r"(z));
    asm("prmt.b32 %0, %1, %2, 0x3244;" : "=r"(hi) : "r"(w), "r"(z));
    ull d; asm("mov.b64 %0, {%1, %2};" : "=l"(d) : "r"(lo), "r"(hi));
    return d;
}
__device__ __forceinline__ float sigf(float x)     { return __fdividef(1.f, 1.f + __expf(-x)); }
__device__ __forceinline__ float tanhfast(float x) { return __fdividef(2.f, 1.f + __expf(-2.f * x)) - 1.f; }

// ---------------- dataflow sync primitives ----------------
__device__ __forceinline__ void wait_all(unsigned target, int tid) {
    if (tid < NBLK) {
        const unsigned* p = &g_cnt[tid * 32];
        unsigned v;
        do {
            asm volatile("ld.acquire.gpu.u32 %0, [%1];" : "=r"(v) : "l"(p) : "memory");
        } while (v < target);
    }
    __syncthreads();
}
__device__ __forceinline__ void publish(unsigned val, int b, int tid) {
    __syncthreads();
    if (tid == 0)
        asm volatile("st.release.gpu.u32 [%0], %1;" :: "l"(&g_cnt[b * 32]), "r"(val) : "memory");
}

// ---------------- init: zero h buffers + counters ----------------
__global__ void init_kernel() {
    int i = blockIdx.x * blockDim.x + threadIdx.x;
    if (i < 2 * H)          g_h_t[i] = 0.f;
    else if (i < 4 * H)     g_h_a[i - 2 * H] = 0.f;
    else if (i < 4 * H + NBLK * 32) g_cnt[i - 4 * H] = 0u;
}

// ---------------- title x-GEMM: pair-packed f32x2, own rows only ----------------
__device__ __forceinline__ void title_xgemm(const int* __restrict__ xt,
                                            const float* __restrict__ emb,
                                            const float* __restrict__ Wih,
                                            const float* __restrict__ bih,
                                            const float* __restrict__ bhh,
                                            unsigned char* dynsm,
                                            int u0, int nu, int tid, int warp, int lane) {
    float*  Xp = (float*)dynsm;                               // float4[32 pairs][257]
    float4* wd = (float4*)(dynsm + 131584) + warp * 258;      // 256 used per warp
    const int nrows = 4 * nu;
    for (int tile = 0; tile < 2; tile++) {
        const int tbase = tile * 64;
        for (int kh = 0; kh < 2; kh++) {
            const int kbase = kh * 512;
            __syncthreads();
            for (int e = tid; e < 64 * 512; e += NT) {
                int k = e & 511, t = e >> 9;
                float v = __ldg(emb + (size_t)__ldg(xt + tbase + t) * E + kbase + k);
                Xp[((t >> 1) * 257 + (k >> 1)) * 4 + ((k & 1) << 1) + (t & 1)] = v;
            }
            __syncthreads();
            for (int r = warp; r < nrows; r += 16) {
                int ul = r >> 2, g = r & 3;
                int grow = g * H + u0 + ul;
                const float4* w4 = (const float4*)(Wih + (size_t)grow * E + kbase);
#pragma unroll
                for (int j = 0; j < 4; j++) {
                    float4 w = __ldg(w4 + ((j << 5) + lane));
                    int o = ((j << 5) + lane) * 2;
                    wd[o]     = make_float4(w.x, w.x, w.y, w.y);
                    wd[o + 1] = make_float4(w.z, w.z, w.w, w.w);
                }
                __syncwarp();
                const ulonglong2* xr = (const ulonglong2*)((const float4*)Xp + lane * 257);
                const ulonglong2* wr = (const ulonglong2*)wd;
                ull acc = 0;
#pragma unroll 8
                for (int j = 0; j < 256; j++) {
                    ulonglong2 w2 = wr[j], x2 = xr[j];
                    ffma2(acc, w2.x, x2.x);
                    ffma2(acc, w2.y, x2.y);
                }
                float a0, a1;
                unpackf2(acc, a0, a1);
                int t0 = tbase + 2 * lane;
                if (kh == 0) {
                    g_gx_t[(size_t)t0 * G + grow]       = a0;
                    g_gx_t[(size_t)(t0 + 1) * G + grow] = a1;
                } else {
                    float bias = __ldg(bih + grow) + __ldg(bhh + grow);
                    g_gx_t[(size_t)t0 * G + grow]       += a0 + bias;
                    g_gx_t[(size_t)(t0 + 1) * G + grow] += a1 + bias;
                }
                __syncwarp();
            }
        }
    }
    __syncthreads();
}

// ---------------- author x-GEMM: 8 pairs, split-K across lane quadrants ----------------
__device__ __forceinline__ void auth_xgemm(const int* __restrict__ xa,
                                           const float* __restrict__ emb,
                                           const float* __restrict__ Wih,
                                           const float* __restrict__ bih,
                                           const float* __restrict__ bhh,
                                           unsigned char* dynsm,
                                           int u0, int nu, int tid, int warp, int lane) {
    float*  Xp = (float*)dynsm;                               // float4[8 pairs][513]
    float4* wd = (float4*)(dynsm + 65664) + warp * 520;       // 512 used per warp
    const int nrows = 4 * nu;
    __syncthreads();
    for (int e = tid; e < 16 * 1024; e += NT) {
        int k = e & 1023, t = e >> 10;
        float v = __ldg(emb + (size_t)__ldg(xa + t) * E + k);
        Xp[((t >> 1) * 513 + (k >> 1)) * 4 + ((k & 1) << 1) + (t & 1)] = v;
    }
    __syncthreads();
    const int p = lane & 7, q = lane >> 3;
    for (int r = warp; r < nrows; r += 16) {
        int ul = r >> 2, g = r & 3;
        int grow = g * H + u0 + ul;
        const float4* w4 = (const float4*)(Wih + (size_t)grow * E);
#pragma unroll
        for (int j = 0; j < 8; j++) {
            float4 w = __ldg(w4 + ((j << 5) + lane));
            int o = ((j << 5) + lane) * 2;
            wd[o]     = make_float4(w.x, w.x, w.y, w.y);
            wd[o + 1] = make_float4(w.z, w.z, w.w, w.w);
        }
        __syncwarp();
        const ulonglong2* xr = (const ulonglong2*)((const float4*)Xp + p * 513 + q * 128);
        const ulonglong2* wr = (const ulonglong2*)(wd + q * 128);
        ull acc = 0;
#pragma unroll 8
        for (int j = 0; j < 128; j++) {
            ulonglong2 w2 = wr[j], x2 = xr[j];
            ffma2(acc, w2.x, x2.x);
            ffma2(acc, w2.y, x2.y);
        }
        float a0, a1;
        unpackf2(acc, a0, a1);
        a0 += __shfl_xor_sync(0xFFFFFFFFu, a0, 8);
        a0 += __shfl_xor_sync(0xFFFFFFFFu, a0, 16);
        a1 += __shfl_xor_sync(0xFFFFFFFFu, a1, 8);
        a1 += __shfl_xor_sync(0xFFFFFFFFu, a1, 16);
        if (q == 0) {
            float bias = __ldg(bih + grow) + __ldg(bhh + grow);
            g_gx_a[(size_t)(2 * p) * G + grow]     = a0 + bias;
            g_gx_a[(size_t)(2 * p + 1) * G + grow] = a1 + bias;
        }
        __syncwarp();
    }
    __syncthreads();
}

// ---------------- recurrence helpers ----------------
__device__ __forceinline__ void load_hp_smem(ull hp[32], const float4* sA, const float4* sB, int lane) {
#pragma unroll
    for (int k = 0; k < 8; k++) {
        int c = (k << 5) + lane;
        float4 f0 = sA[c], f1 = sB[c];
        hp[4 * k + 0] = packf2(f0.x, f0.y);
        hp[4 * k + 1] = packf2(f0.z, f0.w);
        hp[4 * k + 2] = packf2(f1.x, f1.y);
        hp[4 * k + 3] = packf2(f1.z, f1.w);
    }
}
__device__ __forceinline__ void load_hp_gmem(ull hp[32], const float* __restrict__ h, int lane) {
    const float4* h4 = (const float4*)h;
#pragma unroll
    for (int k = 0; k < 8; k++) {
        float4 f0 = __ldcg(h4 + ((k << 6) + (lane << 1)));
        float4 f1 = __ldcg(h4 + ((k << 6) + (lane << 1) + 1));
        hp[4 * k + 0] = packf2(f0.x, f0.y);
        hp[4 * k + 1] = packf2(f0.z, f0.w);
        hp[4 * k + 2] = packf2(f1.x, f1.y);
        hp[4 * k + 3] = packf2(f1.z, f1.w);
    }
}

template<bool SMEM>
__device__ __forceinline__ void unit_step(const __nv_bfloat16* __restrict__ wbase, size_t gstride,
                                          const ull hp[32], const float* __restrict__ gx,
                                          int u, float& c, float* __restrict__ hout, int lane) {
    float s[4];
#pragma unroll
    for (int g = 0; g < 4; g++) {
        const uint4* w = (const uint4*)(wbase + gstride * g);
        ull a0 = 0, a1 = 0, a2 = 0, a3 = 0;
        if (SMEM) {
#pragma unroll
            for (int j = 0; j < 8; j++) {
                uint4 v = w[(j << 5) + lane];
                ffma2(a0, b2f2(v.x), hp[4 * j + 0]);
                ffma2(a1, b2f2(v.y), hp[4 * j + 1]);
                ffma2(a2, b2f2(v.z), hp[4 * j + 2]);
                ffma2(a3, b2f2(v.w), hp[4 * j + 3]);
            }
        } else {
            uint4 v[8];
#pragma unroll
            for (int j = 0; j < 8; j++) v[j] = __ldcg(w + ((j << 5) + lane));
#pragma unroll
            for (int j = 0; j < 8; j++) {
                ffma2(a0, b2f2(v[j].x), hp[4 * j + 0]);
                ffma2(a1, b2f2(v[j].y), hp[4 * j + 1]);
                ffma2(a2, b2f2(v[j].z), hp[4 * j + 2]);
                ffma2(a3, b2f2(v[j].w), hp[4 * j + 3]);
            }
        }
        float x, y;
        unpackf2(addf2(addf2(a0, a1), addf2(a2, a3)), x, y);
        s[g] = x + y;
    }
#pragma unroll
    for (int g = 0; g < 4; g++)
#pragma unroll
        for (int off = 16; off; off >>= 1) s[g] += __shfl_xor_sync(0xFFFFFFFFu, s[g], off);
    if (lane == 0) {
        float gi = s[0] + __ldcg(gx + 0 * H + u);
        float gf = s[1] + __ldcg(gx + 1 * H + u);
        float gg = s[2] + __ldcg(gx + 2 * H + u);
        float go = s[3] + __ldcg(gx + 3 * H + u);
        float iv = sigf(gi), fv = sigf(gf), gv = tanhfast(gg), ov = sigf(go);
        float cn = fv * c + iv * gv;
        c = cn;
        __stcg(hout + u, ov * tanhfast(cn));
    }
}

__device__ __forceinline__ float warp_dot(const float* __restrict__ Wrow,
                                          const float* __restrict__ shv, int K, int lane) {
    const float4* w4 = (const float4*)Wrow;
    const float4* s4 = (const float4*)shv;
    float acc = 0.f;
    for (int i = lane; i < K / 4; i += 32) {
        float4 w = __ldg(w4 + i), x = s4[i];
        acc = fmaf(w.x, x.x, fmaf(w.y, x.y, fmaf(w.z, x.z, fmaf(w.w, x.w, acc))));
    }
#pragma unroll
    for (int off = 16; off; off >>= 1) acc += __shfl_xor_sync(0xFFFFFFFFu, acc, off);
    return acc;
}

// ---------------- the single persistent kernel ----------------
__global__ __launch_bounds__(NT, 1) void mono_kernel(
        const int* __restrict__ xt, const int* __restrict__ xa,
        const float* __restrict__ emb_t, const float* __restrict__ emb_a,
        const float* __restrict__ Wih_t, const float* __restrict__ Whh_t,
        const float* __restrict__ bih_t, const float* __restrict__ bhh_t,
        const float* __restrict__ Wih_a, const float* __restrict__ Whh_a,
        const float* __restrict__ bih_a, const float* __restrict__ bhh_a,
        const float* __restrict__ W1, const float* __restrict__ b1,
        const float* __restrict__ W2, const float* __restrict__ b2,
        const float* __restrict__ W3, const float* __restrict__ b3,
        float* __restrict__ out) {
    extern __shared__ __align__(16) unsigned char dynsm[];
    __nv_bfloat16* ws = (__nv_bfloat16*)dynsm;                // title weights (recurrence)
    float4* sA = (float4*)(dynsm + HS_OFF);                   // split h stage (256 entries)
    float4* sB = sA + 256;
    float* mstage = (float*)dynsm;                            // MLP stage

    const int tid = threadIdx.x, warp = tid >> 5, lane = tid & 31;
    const int b = blockIdx.x;
    const int u0 = (b * 512) / 37;                            // balanced 13-14 units/block
    const int nu = ((b + 1) * 512) / 37 - u0;
    const int n_sm = (nu < 13) ? nu : 13;

    // ---- Phase 0: x-side GEMMs (own rows only) ----
    title_xgemm(xt, emb_t, Wih_t, bih_t, bhh_t, dynsm, u0, nu, tid, warp, lane);
    auth_xgemm(xa, emb_a, Wih_a, bih_a, bhh_a, dynsm, u0, nu, tid, warp, lane);

    // ---- Phase 1: weight conversions ----
    {   // title units 0..n_sm-1 -> smem bf16 (unit-major)
        unsigned* wsu = (unsigned*)ws;
        const int total = n_sm * 4 * (H / 2);
        for (int e = tid; e < total; e += NT) {
            int sr = e >> 10, wd_ = e & 1023;
            int ul = sr >> 2, g = sr & 3;
            float2 v = *(const float2*)(Whh_t + ((size_t)g * H + u0 + ul) * H + 2 * wd_);
            __nv_bfloat162 p = __float22bfloat162_rn(v);
            wsu[(sr << 10) + wd_] = *(unsigned*)&p;
        }
    }
    if (nu == 14) {   // 14th title unit -> per-block global bf16
        unsigned* dst = (unsigned*)g_Wt13_bf + (size_t)b * 4 * (H / 2);
        for (int e = tid; e < 4 * (H / 2); e += NT) {
            int g = e >> 10, wd_ = e & 1023;
            float2 v = *(const float2*)(Whh_t + ((size_t)g * H + u0 + 13) * H + 2 * wd_);
            __nv_bfloat162 p = __float22bfloat162_rn(v);
            dst[(g << 10) + wd_] = *(unsigned*)&p;
        }
    }
    {   // authors: cooperative full-matrix fp32 -> bf16
        const float2* src = (const float2*)Whh_a;
        unsigned* dst = (unsigned*)g_Wa_bf;
        for (size_t i = (size_t)b * NT + tid; i < WELEM / 2; i += (size_t)NBLK * NT) {
            float2 v = src[i];
            __nv_bfloat162 p = __float22bfloat162_rn(v);
            dst[i] = *(unsigned*)&p;
        }
    }
    float cT = 0.f, cA = 0.f;                  // per-warp cell state (lane 0 authoritative)
    publish(1, b, tid);                        // prologue done

    // ---- Phase 2: recurrence (dataflow sync, no grid barrier) ----
    for (int t = 0; t < TT; t++) {
        wait_all((unsigned)(t + 1), tid);      // all producers published h_t
        {   // stage title h into split smem
            const float4* s4 = (const float4*)(g_h_t + (size_t)(t & 1) * H);
            for (int i = tid; i < 256; i += NT) {
                sA[i] = __ldcg(s4 + 2 * i);
                sB[i] = __ldcg(s4 + 2 * i + 1);
            }
        }
        __syncthreads();
        const float* gxT = g_gx_t + (size_t)t * G;
        float* hdT = g_h_t + (size_t)((t + 1) & 1) * H;
        if (warp < n_sm) {
            ull hp[32];
            load_hp_smem(hp, sA, sB, lane);
            unit_step<true>(ws + (size_t)(warp * 4) * H, (size_t)H,
                            hp, gxT, u0 + warp, cT, hdT, lane);
        } else if (warp == 13 && nu == 14) {
            ull hp[32];
            load_hp_smem(hp, sA, sB, lane);
            unit_step<false>(g_Wt13_bf + (size_t)b * 4 * H, (size_t)H,
                             hp, gxT, u0 + 13, cT, hdT, lane);
        }
        if (t < TA && warp < nu) {
            ull hp[32];
            load_hp_gmem(hp, g_h_a + (size_t)(t & 1) * H, lane);
            unit_step<false>(g_Wa_bf + (size_t)(u0 + warp) * H, (size_t)H * H,
                             hp, g_gx_a + (size_t)t * G, u0 + warp, cA,
                             g_h_a + (size_t)((t + 1) & 1) * H, lane);
        }
        publish((unsigned)(t + 2), b, tid);
    }
    // final hT in g_h_t[0], final hA in g_h_a[0]  (TT, TA even)

    // ---- Phase 3: MLP head (same dataflow sync) ----
    wait_all((unsigned)(TT + 1), tid);
    {
        const float4* t4 = (const float4*)g_h_t;
        const float4* a4 = (const float4*)g_h_a;
        float4* d4 = (float4*)mstage;
        for (int i = tid; i < H / 4; i += NT) {
            d4[i]         = __ldcg(t4 + i);
            d4[H / 4 + i] = __ldcg(a4 + i);
        }
        __syncthreads();
        if (warp < nu) {
            int row = u0 + warp;
            float s = warp_dot(W1 + (size_t)row * 2 * H, mstage, 2 * H, lane);
            if (lane == 0) __stcg(&g_h1[row], fmaxf(s + __ldg(b1 + row), 0.f));
        }
    }
    publish((unsigned)(TT + 2), b, tid);
    wait_all((unsigned)(TT + 2), tid);
    {
        const float4* s4 = (const float4*)g_h1;
        float4* d4 = (float4*)mstage;
        for (int i = tid; i < H / 4; i += NT) d4[i] = __ldcg(s4 + i);
        __syncthreads();
        if (warp < nu) {
            int row = u0 + warp;
            float s = warp_dot(W2 + (size_t)row * H, mstage, H, lane);
            if (lane == 0) __stcg(&g_h2[row], fmaxf(s + __ldg(b2 + row), 0.f));
        }
    }
    publish((unsigned)(TT + 3), b, tid);
    if (b == 0) {
        wait_all((unsigned)(TT + 3), tid);
        const float4* s4 = (const float4*)g_h2;
        float4* d4 = (float4*)mstage;
        for (int i = tid; i < H / 4; i += NT) d4[i] = __ldcg(s4 + i);
        __syncthreads();
        if (warp < 2) {
            float s = warp_dot(W3 + (size_t)warp * H, mstage, H, lane);
            if (lane == 0) out[warp] = s + __ldg(b3 + warp);
        }
    }
}

// ---------------- launcher ----------------
extern "C" void kernel_launch(void* const* d_in, const int* in_sizes, int n_in,
                              void* d_out, int out_size) {
    const int*   x_title   = (const int*)  d_in[0];
    const int*   x_authors = (const int*)  d_in[1];
    const float* emb_t     = (const float*)d_in[2];
    const float* emb_a     = (const float*)d_in[3];
    const float* W_ih_t    = (const float*)d_in[4];
    const float* W_hh_t    = (const float*)d_in[5];
    const float* b_ih_t    = (const float*)d_in[6];
    const float* b_hh_t    = (const float*)d_in[7];
    const float* W_ih_a    = (const float*)d_in[8];
    const float* W_hh_a    = (const float*)d_in[9];
    const float* b_ih_a    = (const float*)d_in[10];
    const float* b_hh_a    = (const float*)d_in[11];
    const float* W1        = (const float*)d_in[12];
    const float* b1        = (const float*)d_in[13];
    const float* W2        = (const float*)d_in[14];
    const float* b2        = (const float*)d_in[15];
    const float* W3        = (const float*)d_in[16];
    const float* b3        = (const float*)d_in[17];
    float* out = (float*)d_out;

    static int smem_set = 0;
    if (!smem_set) {
        cudaFuncSetAttribute(mono_kernel,
                             cudaFuncAttributeMaxDynamicSharedMemorySize, DYN_SMEM);
        smem_set = 1;
    }

    init_kernel<<<64, 256>>>();
    mono_kernel<<<NBLK, NT, DYN_SMEM>>>(x_title, x_authors, emb_t, emb_a,
                                        W_ih_t, W_hh_t, b_ih_t, b_hh_t,
                                        W_ih_a, W_hh_a, b_ih_a, b_hh_a,
                                        W1, b1, W2, b2, W3, b3, out);
}

// round 17
// speedup vs baseline: 1.4373x; 1.0607x over previous
#include <cuda_runtime.h>
#include <cuda_bf16.h>
#include <math.h>

// Problem dims (fixed by the reference)
#define E     1024
#define H     2048
#define G     8192     // 4*H gate rows
#define TT    128      // title timesteps
#define TA    16       // author timesteps
#define NBLK  148      // persistent grid: one block per SM
#define NT    512      // threads per block (16 warps)
#define WELEM ((size_t)G * H)
#define WS_BYTES (13 * 4 * H * 2)           // 212992 B smem title weights (13 units)
#define HS_OFF   WS_BYTES                   // 8 KB split h staging
#define DYN_SMEM (WS_BYTES + 2 * H * 4)     // 221184 B

// ---------------- device scratch (no allocation allowed) ----------------
__device__ __align__(16) float g_gx_t[TT * G];
__device__ __align__(16) float g_gx_a[TA * G];
__device__ __align__(16) __nv_bfloat16 g_Wa_bf[WELEM];          // authors bf16 (32 MB)
__device__ __align__(16) __nv_bfloat16 g_Wt13_bf[NBLK * 4 * H]; // per-block 14th title unit
__device__ __align__(16) float g_h_t[2 * H];
__device__ __align__(16) float g_h_a[2 * H];
__device__ __align__(16) float g_h1[H];
__device__ __align__(16) float g_h2[H];
__device__ unsigned g_cnt[NBLK * 32];       // one padded line per block

// ---------------- packed f32x2 + bf16 helpers ----------------
typedef unsigned long long ull;
__device__ __forceinline__ ull packf2(float x, float y) {
    ull d; asm("mov.b64 %0, {%1, %2};" : "=l"(d) : "f"(x), "f"(y)); return d;
}
__device__ __forceinline__ void unpackf2(ull d, float& x, float& y) {
    asm("mov.b64 {%0, %1}, %2;" : "=f"(x), "=f"(y) : "l"(d));
}
__device__ __forceinline__ void ffma2(ull& d, ull a, ull b) {
    asm("fma.rn.f32x2 %0, %1, %2, %0;" : "+l"(d) : "l"(a), "l"(b));
}
__device__ __forceinline__ ull addf2(ull a, ull b) {
    ull d; asm("add.rn.f32x2 %0, %1, %2;" : "=l"(d) : "l"(a), "l"(b)); return d;
}
// flavor A: bf16x2 -> f32x2 via 2 PRMT (alu pipe)
__device__ __forceinline__ ull b2f2(unsigned w) {
    unsigned lo, hi, z = 0u;
    asm("prmt.b32 %0, %1, %2, 0x1044;" : "=r"(lo) : "r"(w), "r"(z));
    asm("prmt.b32 %0, %1, %2, 0x3244;" : "=r"(hi) : "r"(w), "r"(z));
    ull d; asm("mov.b64 %0, {%1, %2};" : "=l"(d) : "r"(lo), "r"(hi));
    return d;
}
// flavor B: bit-identical, IMAD (fma pipe) + LOP3 (alu pipe) -> balances pipes
__device__ __forceinline__ ull b2f2_b(unsigned w) {
    unsigned lo, hi;
    asm("mad.lo.u32 %0, %1, %2, %3;" : "=r"(lo) : "r"(w), "r"(65536u), "r"(0u));
    asm("and.b32 %0, %1, 0xFFFF0000;" : "=r"(hi) : "r"(w));
    ull d; asm("mov.b64 %0, {%1, %2};" : "=l"(d) : "r"(lo), "r"(hi));
    return d;
}
__device__ __forceinline__ float sigf(float x)     { return __fdividef(1.f, 1.f + __expf(-x)); }
__device__ __forceinline__ float tanhfast(float x) { return __fdividef(2.f, 1.f + __expf(-2.f * x)) - 1.f; }

// ---------------- dataflow sync primitives ----------------
__device__ __forceinline__ void wait_all(unsigned target, int tid) {
    if (tid < NBLK) {
        const unsigned* p = &g_cnt[tid * 32];
        unsigned v;
        do {
            asm volatile("ld.acquire.gpu.u32 %0, [%1];" : "=r"(v) : "l"(p) : "memory");
        } while (v < target);
    }
    __syncthreads();
}
__device__ __forceinline__ void publish(unsigned val, int b, int tid) {
    __syncthreads();
    if (tid == 0)
        asm volatile("st.release.gpu.u32 [%0], %1;" :: "l"(&g_cnt[b * 32]), "r"(val) : "memory");
}

// ---------------- init: zero h buffers + counters ----------------
__global__ void init_kernel() {
    int i = blockIdx.x * blockDim.x + threadIdx.x;
    if (i < 2 * H)          g_h_t[i] = 0.f;
    else if (i < 4 * H)     g_h_a[i - 2 * H] = 0.f;
    else if (i < 4 * H + NBLK * 32) g_cnt[i - 4 * H] = 0u;
}

// ---------------- title x-GEMM: pair-packed f32x2, own rows only ----------------
__device__ __forceinline__ void title_xgemm(const int* __restrict__ xt,
                                            const float* __restrict__ emb,
                                            const float* __restrict__ Wih,
                                            const float* __restrict__ bih,
                                            const float* __restrict__ bhh,
                                            unsigned char* dynsm,
                                            int u0, int nu, int tid, int warp, int lane) {
    float*  Xp = (float*)dynsm;                               // float4[32 pairs][257]
    float4* wd = (float4*)(dynsm + 131584) + warp * 258;      // 256 used per warp
    const int nrows = 4 * nu;
    for (int tile = 0; tile < 2; tile++) {
        const int tbase = tile * 64;
        for (int kh = 0; kh < 2; kh++) {
            const int kbase = kh * 512;
            __syncthreads();
            for (int e = tid; e < 64 * 512; e += NT) {
                int k = e & 511, t = e >> 9;
                float v = __ldg(emb + (size_t)__ldg(xt + tbase + t) * E + kbase + k);
                Xp[((t >> 1) * 257 + (k >> 1)) * 4 + ((k & 1) << 1) + (t & 1)] = v;
            }
            __syncthreads();
            for (int r = warp; r < nrows; r += 16) {
                int ul = r >> 2, g = r & 3;
                int grow = g * H + u0 + ul;
                const float4* w4 = (const float4*)(Wih + (size_t)grow * E + kbase);
#pragma unroll
                for (int j = 0; j < 4; j++) {
                    float4 w = __ldg(w4 + ((j << 5) + lane));
                    int o = ((j << 5) + lane) * 2;
                    wd[o]     = make_float4(w.x, w.x, w.y, w.y);
                    wd[o + 1] = make_float4(w.z, w.z, w.w, w.w);
                }
                __syncwarp();
                const ulonglong2* xr = (const ulonglong2*)((const float4*)Xp + lane * 257);
                const ulonglong2* wr = (const ulonglong2*)wd;
                ull acc = 0;
#pragma unroll 8
                for (int j = 0; j < 256; j++) {
                    ulonglong2 w2 = wr[j], x2 = xr[j];
                    ffma2(acc, w2.x, x2.x);
                    ffma2(acc, w2.y, x2.y);
                }
                float a0, a1;
                unpackf2(acc, a0, a1);
                int t0 = tbase + 2 * lane;
                if (kh == 0) {
                    g_gx_t[(size_t)t0 * G + grow]       = a0;
                    g_gx_t[(size_t)(t0 + 1) * G + grow] = a1;
                } else {
                    float bias = __ldg(bih + grow) + __ldg(bhh + grow);
                    g_gx_t[(size_t)t0 * G + grow]       += a0 + bias;
                    g_gx_t[(size_t)(t0 + 1) * G + grow] += a1 + bias;
                }
                __syncwarp();
            }
        }
    }
    __syncthreads();
}

// ---------------- author x-GEMM: 8 pairs, split-K across lane quadrants ----------------
__device__ __forceinline__ void auth_xgemm(const int* __restrict__ xa,
                                           const float* __restrict__ emb,
                                           const float* __restrict__ Wih,
                                           const float* __restrict__ bih,
                                           const float* __restrict__ bhh,
                                           unsigned char* dynsm,
                                           int u0, int nu, int tid, int warp, int lane) {
    float*  Xp = (float*)dynsm;                               // float4[8 pairs][513]
    float4* wd = (float4*)(dynsm + 65664) + warp * 520;       // 512 used per warp
    const int nrows = 4 * nu;
    __syncthreads();
    for (int e = tid; e < 16 * 1024; e += NT) {
        int k = e & 1023, t = e >> 10;
        float v = __ldg(emb + (size_t)__ldg(xa + t) * E + k);
        Xp[((t >> 1) * 513 + (k >> 1)) * 4 + ((k & 1) << 1) + (t & 1)] = v;
    }
    __syncthreads();
    const int p = lane & 7, q = lane >> 3;
    for (int r = warp; r < nrows; r += 16) {
        int ul = r >> 2, g = r & 3;
        int grow = g * H + u0 + ul;
        const float4* w4 = (const float4*)(Wih + (size_t)grow * E);
#pragma unroll
        for (int j = 0; j < 8; j++) {
            float4 w = __ldg(w4 + ((j << 5) + lane));
            int o = ((j << 5) + lane) * 2;
            wd[o]     = make_float4(w.x, w.x, w.y, w.y);
            wd[o + 1] = make_float4(w.z, w.z, w.w, w.w);
        }
        __syncwarp();
        const ulonglong2* xr = (const ulonglong2*)((const float4*)Xp + p * 513 + q * 128);
        const ulonglong2* wr = (const ulonglong2*)(wd + q * 128);
        ull acc = 0;
#pragma unroll 8
        for (int j = 0; j < 128; j++) {
            ulonglong2 w2 = wr[j], x2 = xr[j];
            ffma2(acc, w2.x, x2.x);
            ffma2(acc, w2.y, x2.y);
        }
        float a0, a1;
        unpackf2(acc, a0, a1);
        a0 += __shfl_xor_sync(0xFFFFFFFFu, a0, 8);
        a0 += __shfl_xor_sync(0xFFFFFFFFu, a0, 16);
        a1 += __shfl_xor_sync(0xFFFFFFFFu, a1, 8);
        a1 += __shfl_xor_sync(0xFFFFFFFFu, a1, 16);
        if (q == 0) {
            float bias = __ldg(bih + grow) + __ldg(bhh + grow);
            g_gx_a[(size_t)(2 * p) * G + grow]     = a0 + bias;
            g_gx_a[(size_t)(2 * p + 1) * G + grow] = a1 + bias;
        }
        __syncwarp();
    }
    __syncthreads();
}

// ---------------- recurrence helpers ----------------
__device__ __forceinline__ void load_hp_smem(ull hp[32], const float4* sA, const float4* sB, int lane) {
#pragma unroll
    for (int k = 0; k < 8; k++) {
        int c = (k << 5) + lane;
        float4 f0 = sA[c], f1 = sB[c];
        hp[4 * k + 0] = packf2(f0.x, f0.y);
        hp[4 * k + 1] = packf2(f0.z, f0.w);
        hp[4 * k + 2] = packf2(f1.x, f1.y);
        hp[4 * k + 3] = packf2(f1.z, f1.w);
    }
}
__device__ __forceinline__ void load_hp_gmem(ull hp[32], const float* __restrict__ h, int lane) {
    const float4* h4 = (const float4*)h;
#pragma unroll
    for (int k = 0; k < 8; k++) {
        float4 f0 = __ldcg(h4 + ((k << 6) + (lane << 1)));
        float4 f1 = __ldcg(h4 + ((k << 6) + (lane << 1) + 1));
        hp[4 * k + 0] = packf2(f0.x, f0.y);
        hp[4 * k + 1] = packf2(f0.z, f0.w);
        hp[4 * k + 2] = packf2(f1.x, f1.y);
        hp[4 * k + 3] = packf2(f1.z, f1.w);
    }
}

// accumulate one uint4 of bf16x2 weights (balanced conversion flavors by j parity)
#define ACC_V(v, jj)                                                     \
    do {                                                                 \
        if ((jj) & 1) {                                                  \
            ffma2(a0, b2f2((v).x),   hp[4 * (jj) + 0]);                  \
            ffma2(a1, b2f2((v).y),   hp[4 * (jj) + 1]);                  \
            ffma2(a2, b2f2((v).z),   hp[4 * (jj) + 2]);                  \
            ffma2(a3, b2f2((v).w),   hp[4 * (jj) + 3]);                  \
        } else {                                                         \
            ffma2(a0, b2f2_b((v).x), hp[4 * (jj) + 0]);                  \
            ffma2(a1, b2f2_b((v).y), hp[4 * (jj) + 1]);                  \
            ffma2(a2, b2f2_b((v).z), hp[4 * (jj) + 2]);                  \
            ffma2(a3, b2f2_b((v).w), hp[4 * (jj) + 3]);                  \
        }                                                                \
    } while (0)

template<bool SMEM>
__device__ __forceinline__ void unit_step(const __nv_bfloat16* __restrict__ wbase, size_t gstride,
                                          const ull hp[32], const float* __restrict__ gxslot,
                                          float& c, float* __restrict__ hdst, int lane) {
    float s[4];
#pragma unroll
    for (int g = 0; g < 4; g++) {
        const uint4* w = (const uint4*)(wbase + gstride * g);
        ull a0 = 0, a1 = 0, a2 = 0, a3 = 0;
        if (SMEM) {
#pragma unroll
            for (int j = 0; j < 8; j++) {
                uint4 v = w[(j << 5) + lane];
                ACC_V(v, j);
            }
        } else {
            uint4 v[8];
#pragma unroll
            for (int j = 0; j < 8; j++) v[j] = __ldcg(w + ((j << 5) + lane));
#pragma unroll
            for (int j = 0; j < 8; j++) ACC_V(v[j], j);
        }
        float x, y;
        unpackf2(addf2(addf2(a0, a1), addf2(a2, a3)), x, y);
        s[g] = x + y;
    }
#pragma unroll
    for (int g = 0; g < 4; g++)
#pragma unroll
        for (int off = 16; off; off >>= 1) s[g] += __shfl_xor_sync(0xFFFFFFFFu, s[g], off);
    if (lane == 0) {
        float gi = s[0] + gxslot[0];
        float gf = s[1] + gxslot[1];
        float gg = s[2] + gxslot[2];
        float go = s[3] + gxslot[3];
        float iv = sigf(gi), fv = sigf(gf), gv = tanhfast(gg), ov = sigf(go);
        float cn = fv * c + iv * gv;
        c = cn;
        __stcg(hdst, ov * tanhfast(cn));
    }
}

// two global-bf16 rows (unit-13 halves); returns lane-0 reduced sums
__device__ __forceinline__ void rows2_global(const __nv_bfloat16* __restrict__ w2,
                                             const ull hp[32], int lane, float s[2]) {
#pragma unroll
    for (int r = 0; r < 2; r++) {
        const uint4* w = (const uint4*)(w2 + (size_t)r * H);
        uint4 v[8];
#pragma unroll
        for (int j = 0; j < 8; j++) v[j] = __ldcg(w + ((j << 5) + lane));
        ull a0 = 0, a1 = 0, a2 = 0, a3 = 0;
#pragma unroll
        for (int j = 0; j < 8; j++) ACC_V(v[j], j);
        float x, y;
        unpackf2(addf2(addf2(a0, a1), addf2(a2, a3)), x, y);
        s[r] = x + y;
    }
#pragma unroll
    for (int off = 16; off; off >>= 1) {
        s[0] += __shfl_xor_sync(0xFFFFFFFFu, s[0], off);
        s[1] += __shfl_xor_sync(0xFFFFFFFFu, s[1], off);
    }
}

__device__ __forceinline__ float warp_dot(const float* __restrict__ Wrow,
                                          const float* __restrict__ shv, int K, int lane) {
    const float4* w4 = (const float4*)Wrow;
    const float4* s4 = (const float4*)shv;
    float acc = 0.f;
    for (int i = lane; i < K / 4; i += 32) {
        float4 w = __ldg(w4 + i), x = s4[i];
        acc = fmaf(w.x, x.x, fmaf(w.y, x.y, fmaf(w.z, x.z, fmaf(w.w, x.w, acc))));
    }
#pragma unroll
    for (int off = 16; off; off >>= 1) acc += __shfl_xor_sync(0xFFFFFFFFu, acc, off);
    return acc;
}

// ---------------- the single persistent kernel ----------------
__global__ __launch_bounds__(NT, 1) void mono_kernel(
        const int* __restrict__ xt, const int* __restrict__ xa,
        const float* __restrict__ emb_t, const float* __restrict__ emb_a,
        const float* __restrict__ Wih_t, const float* __restrict__ Whh_t,
        const float* __restrict__ bih_t, const float* __restrict__ bhh_t,
        const float* __restrict__ Wih_a, const float* __restrict__ Whh_a,
        const float* __restrict__ bih_a, const float* __restrict__ bhh_a,
        const float* __restrict__ W1, const float* __restrict__ b1,
        const float* __restrict__ W2, const float* __restrict__ b2,
        const float* __restrict__ W3, const float* __restrict__ b3,
        float* __restrict__ out) {
    extern __shared__ __align__(16) unsigned char dynsm[];
    __nv_bfloat16* ws = (__nv_bfloat16*)dynsm;                // title weights (recurrence)
    float4* sA = (float4*)(dynsm + HS_OFF);                   // split h stage (256 entries)
    float4* sB = sA + 256;
    float* mstage = (float*)dynsm;                            // MLP stage

    __shared__ float s_gx[16][4];     // prefetched title gx per warp
    __shared__ float s_gxa[16][4];    // prefetched author gx per warp
    __shared__ float sg13[4];         // unit-13 gate sums exchange

    const int tid = threadIdx.x, warp = tid >> 5, lane = tid & 31;
    const int b = blockIdx.x;
    const int u0 = (b * 512) / 37;                            // balanced 13-14 units/block
    const int nu = ((b + 1) * 512) / 37 - u0;
    const int n_sm = (nu < 13) ? nu : 13;
    const bool has13 = (nu == 14);
    const int u13 = u0 + 13;

    // ---- Phase 0: x-side GEMMs (own rows only) ----
    title_xgemm(xt, emb_t, Wih_t, bih_t, bhh_t, dynsm, u0, nu, tid, warp, lane);
    auth_xgemm(xa, emb_a, Wih_a, bih_a, bhh_a, dynsm, u0, nu, tid, warp, lane);

    // ---- Phase 1: weight conversions ----
    {   // title units 0..n_sm-1 -> smem bf16 (unit-major)
        unsigned* wsu = (unsigned*)ws;
        const int total = n_sm * 4 * (H / 2);
        for (int e = tid; e < total; e += NT) {
            int sr = e >> 10, wd_ = e & 1023;
            int ul = sr >> 2, g = sr & 3;
            float2 v = *(const float2*)(Whh_t + ((size_t)g * H + u0 + ul) * H + 2 * wd_);
            __nv_bfloat162 p = __float22bfloat162_rn(v);
            wsu[(sr << 10) + wd_] = *(unsigned*)&p;
        }
    }
    if (has13) {   // 14th title unit -> per-block global bf16
        unsigned* dst = (unsigned*)g_Wt13_bf + (size_t)b * 4 * (H / 2);
        for (int e = tid; e < 4 * (H / 2); e += NT) {
            int g = e >> 10, wd_ = e & 1023;
            float2 v = *(const float2*)(Whh_t + ((size_t)g * H + u13) * H + 2 * wd_);
            __nv_bfloat162 p = __float22bfloat162_rn(v);
            dst[(g << 10) + wd_] = *(unsigned*)&p;
        }
    }
    {   // authors: cooperative full-matrix fp32 -> bf16
        const float2* src = (const float2*)Whh_a;
        unsigned* dst = (unsigned*)g_Wa_bf;
        for (size_t i = (size_t)b * NT + tid; i < WELEM / 2; i += (size_t)NBLK * NT) {
            float2 v = src[i];
            __nv_bfloat162 p = __float22bfloat162_rn(v);
            dst[i] = *(unsigned*)&p;
        }
    }
    float cT = 0.f, cA = 0.f, c13 = 0.f;       // per-warp cell state (lane 0 authoritative)
    publish(1, b, tid);                        // prologue done

    // ---- Phase 2: recurrence (dataflow sync, no grid barrier) ----
    for (int t = 0; t < TT; t++) {
        const float* gxT = g_gx_t + (size_t)t * G;
        const float* gxA = g_gx_a + (size_t)t * G;
        // gx prefetch into smem slots (same-thread write/read: no sync needed)
        if (lane == 0) {
            if (warp < n_sm) {
                int u = u0 + warp;
                s_gx[warp][0] = __ldcg(gxT + 0 * H + u);
                s_gx[warp][1] = __ldcg(gxT + 1 * H + u);
                s_gx[warp][2] = __ldcg(gxT + 2 * H + u);
                s_gx[warp][3] = __ldcg(gxT + 3 * H + u);
            } else if (has13 && warp == 13) {
                s_gx[13][0] = __ldcg(gxT + 0 * H + u13);
                s_gx[13][1] = __ldcg(gxT + 1 * H + u13);
            } else if (has13 && warp == 14) {
                s_gx[14][2] = __ldcg(gxT + 2 * H + u13);
                s_gx[14][3] = __ldcg(gxT + 3 * H + u13);
            }
            if (t < TA && warp < nu) {
                int u = u0 + warp;
                s_gxa[warp][0] = __ldcg(gxA + 0 * H + u);
                s_gxa[warp][1] = __ldcg(gxA + 1 * H + u);
                s_gxa[warp][2] = __ldcg(gxA + 2 * H + u);
                s_gxa[warp][3] = __ldcg(gxA + 3 * H + u);
            }
        }
        wait_all((unsigned)(t + 1), tid);      // all producers published h_t
        {   // stage title h into split smem
            const float4* s4 = (const float4*)(g_h_t + (size_t)(t & 1) * H);
            for (int i = tid; i < 256; i += NT) {
                sA[i] = __ldcg(s4 + 2 * i);
                sB[i] = __ldcg(s4 + 2 * i + 1);
            }
        }
        __syncthreads();
        float* hdT = g_h_t + (size_t)((t + 1) & 1) * H;
        if (warp < n_sm) {
            ull hp[32];
            load_hp_smem(hp, sA, sB, lane);
            unit_step<true>(ws + (size_t)(warp * 4) * H, (size_t)H,
                            hp, s_gx[warp], cT, hdT + u0 + warp, lane);
        } else if (has13 && warp == 13) {
            ull hp[32];
            load_hp_smem(hp, sA, sB, lane);
            float s2[2];
            rows2_global(g_Wt13_bf + (size_t)b * 4 * H, hp, lane, s2);
            if (lane == 0) {
                sg13[0] = s2[0] + s_gx[13][0];
                sg13[1] = s2[1] + s_gx[13][1];
            }
            asm volatile("bar.sync 1, 64;" ::: "memory");
        } else if (has13 && warp == 14) {
            ull hp[32];
            load_hp_smem(hp, sA, sB, lane);
            float s2[2];
            rows2_global(g_Wt13_bf + (size_t)b * 4 * H + 2 * H, hp, lane, s2);
            if (lane == 0) {
                sg13[2] = s2[0] + s_gx[14][2];
                sg13[3] = s2[1] + s_gx[14][3];
            }
            asm volatile("bar.sync 1, 64;" ::: "memory");
            if (lane == 0) {
                float iv = sigf(sg13[0]), fv = sigf(sg13[1]);
                float gv = tanhfast(sg13[2]), ov = sigf(sg13[3]);
                float cn = fv * c13 + iv * gv;
                c13 = cn;
                __stcg(hdT + u13, ov * tanhfast(cn));
            }
        }
        if (t < TA && warp < nu) {
            ull hp[32];
            load_hp_gmem(hp, g_h_a + (size_t)(t & 1) * H, lane);
            unit_step<false>(g_Wa_bf + (size_t)(u0 + warp) * H, (size_t)H * H,
                             hp, s_gxa[warp], cA,
                             g_h_a + (size_t)((t + 1) & 1) * H + u0 + warp, lane);
        }
        publish((unsigned)(t + 2), b, tid);
    }
    // final hT in g_h_t[0], final hA in g_h_a[0]  (TT, TA even)

    // ---- Phase 3: MLP head (same dataflow sync) ----
    wait_all((unsigned)(TT + 1), tid);
    {
        const float4* t4 = (const float4*)g_h_t;
        const float4* a4 = (const float4*)g_h_a;
        float4* d4 = (float4*)mstage;
        for (int i = tid; i < H / 4; i += NT) {
            d4[i]         = __ldcg(t4 + i);
            d4[H / 4 + i] = __ldcg(a4 + i);
        }
        __syncthreads();
        if (warp < nu) {
            int row = u0 + warp;
            float s = warp_dot(W1 + (size_t)row * 2 * H, mstage, 2 * H, lane);
            if (lane == 0) __stcg(&g_h1[row], fmaxf(s + __ldg(b1 + row), 0.f));
        }
    }
    publish((unsigned)(TT + 2), b, tid);
    wait_all((unsigned)(TT + 2), tid);
    {
        const float4* s4 = (const float4*)g_h1;
        float4* d4 = (float4*)mstage;
        for (int i = tid; i < H / 4; i += NT) d4[i] = __ldcg(s4 + i);
        __syncthreads();
        if (warp < nu) {
            int row = u0 + warp;
            float s = warp_dot(W2 + (size_t)row * H, mstage, H, lane);
            if (lane == 0) __stcg(&g_h2[row], fmaxf(s + __ldg(b2 + row), 0.f));
        }
    }
    publish((unsigned)(TT + 3), b, tid);
    if (b == 0) {
        wait_all((unsigned)(TT + 3), tid);
        const float4* s4 = (const float4*)g_h2;
        float4* d4 = (float4*)mstage;
        for (int i = tid; i < H / 4; i += NT) d4[i] = __ldcg(s4 + i);
        __syncthreads();
        if (warp < 2) {
            float s = warp_dot(W3 + (size_t)warp * H, mstage, H, lane);
            if (lane == 0) out[warp] = s + __ldg(b3 + warp);
        }
    }
}

// ---------------- launcher ----------------
extern "C" void kernel_launch(void* const* d_in, const int* in_sizes, int n_in,
                              void* d_out, int out_size) {
    const int*   x_title   = (const int*)  d_in[0];
    const int*   x_authors = (const int*)  d_in[1];
    const float* emb_t     = (const float*)d_in[2];
    const float* emb_a     = (const float*)d_in[3];
    const float* W_ih_t    = (const float*)d_in[4];
    const float* W_hh_t    = (const float*)d_in[5];
    const float* b_ih_t    = (const float*)d_in[6];
    const float* b_hh_t    = (const float*)d_in[7];
    const float* W_ih_a    = (const float*)d_in[8];
    const float* W_hh_a    = (const float*)d_in[9];
    const float* b_ih_a    = (const float*)d_in[10];
    const float* b_hh_a    = (const float*)d_in[11];
    const float* W1        = (const float*)d_in[12];
    const float* b1        = (const float*)d_in[13];
    const float* W2        = (const float*)d_in[14];
    const float* b2        = (const float*)d_in[15];
    const float* W3        = (const float*)d_in[16];
    const float* b3        = (const float*)d_in[17];
    float* out = (float*)d_out;

    static int smem_set = 0;
    if (!smem_set) {
        cudaFuncSetAttribute(mono_kernel,
                             cudaFuncAttributeMaxDynamicSharedMemorySize, DYN_SMEM);
        smem_set = 1;
    }

    init_kernel<<<64, 256>>>();
    mono_kernel<<<NBLK, NT, DYN_SMEM>>>(x_title, x_authors, emb_t, emb_a,
                                        W_ih_t, W_hh_t, b_ih_t, b_hh_t,
                                        W_ih_a, W_hh_a, b_ih_a, b_hh_a,
                                        W1, b1, W2, b2, W3, b3, out);
}